// round 1
// baseline (speedup 1.0000x reference)
#include <cuda_runtime.h>
#include <cuda_bf16.h>
#include <cstdint>

using u32 = unsigned int;

// Problem constants: B=16, C=64, H=W=64
static constexpr int B_  = 16;
static constexpr int HW_ = 4096;   // 64*64
static constexpr int SP_ = 1024;   // pooled spatial (32*32)

// ---------------- scratch (__device__ globals; no allocation) ----------------
__device__ __align__(16) __nv_bfloat16 d_theta  [B_ * HW_ * 8];   // [b][p][8]
__device__ __align__(16) __nv_bfloat16 d_phi_pre[B_ * HW_ * 8];   // [b][p][8]  (pre-pool)
__device__ __align__(16) __nv_bfloat16 d_g_pre  [B_ * HW_ * 32];  // [b][p][32] (pre-pool)
__device__ __align__(16) __nv_bfloat16 d_phi_t  [B_ * SP_ * 8];   // [b][s][8]
__device__ __align__(16) __nv_bfloat16 d_g_t    [B_ * 32 * SP_];  // [b][v][s]
__device__ __align__(16) float         d_o      [B_ * HW_ * 32];  // [b][q][32]

// ---------------- small helpers ----------------
__device__ __forceinline__ u32 packbf(float lo, float hi) {
    __nv_bfloat162 v = __float22bfloat162_rn(make_float2(lo, hi));
    return *reinterpret_cast<u32*>(&v);
}
__device__ __forceinline__ uint4 pack8(const float* a) {
    uint4 r;
    r.x = packbf(a[0], a[1]); r.y = packbf(a[2], a[3]);
    r.z = packbf(a[4], a[5]); r.w = packbf(a[6], a[7]);
    return r;
}
__device__ __forceinline__ u32 hmax2u(u32 a, u32 b) {
    __nv_bfloat162 r = __hmax2(*reinterpret_cast<__nv_bfloat162*>(&a),
                               *reinterpret_cast<__nv_bfloat162*>(&b));
    return *reinterpret_cast<u32*>(&r);
}
__device__ __forceinline__ uint4 max4u(uint4 a, uint4 b, uint4 c, uint4 d) {
    uint4 r;
    r.x = hmax2u(hmax2u(a.x, b.x), hmax2u(c.x, d.x));
    r.y = hmax2u(hmax2u(a.y, b.y), hmax2u(c.y, d.y));
    r.z = hmax2u(hmax2u(a.z, b.z), hmax2u(c.z, d.z));
    r.w = hmax2u(hmax2u(a.w, b.w), hmax2u(c.w, d.w));
    return r;
}

// mma.m16n8k8 bf16: S = A(16x8) * B(8x8), C=0
__device__ __forceinline__ void mma_k8(float* d, u32 a0, u32 a1, u32 b0) {
    asm volatile(
        "mma.sync.aligned.m16n8k8.row.col.f32.bf16.bf16.f32 "
        "{%0,%1,%2,%3}, {%4,%5}, {%6}, {%7,%8,%9,%10};\n"
        : "=f"(d[0]), "=f"(d[1]), "=f"(d[2]), "=f"(d[3])
        : "r"(a0), "r"(a1), "r"(b0),
          "f"(0.f), "f"(0.f), "f"(0.f), "f"(0.f));
}
// mma.m16n8k16 bf16: D += A(16x16) * B(16x8)
__device__ __forceinline__ void mma_k16(float* d, u32 a0, u32 a1, u32 a2, u32 a3,
                                        u32 b0, u32 b1) {
    asm volatile(
        "mma.sync.aligned.m16n8k16.row.col.f32.bf16.bf16.f32 "
        "{%0,%1,%2,%3}, {%4,%5,%6,%7}, {%8,%9}, {%0,%1,%2,%3};\n"
        : "+f"(d[0]), "+f"(d[1]), "+f"(d[2]), "+f"(d[3])
        : "r"(a0), "r"(a1), "r"(a2), "r"(a3), "r"(b0), "r"(b1));
}

// ---------------- kernel 1: 1x1 conv projections (theta, phi_pre, g_pre) ----------------
// grid (16, 16) x 256 threads; thread = one pixel; 48 outputs per pixel.
__global__ void __launch_bounds__(256) proj_kernel(
    const float* __restrict__ x,
    const float* __restrict__ Wt, const float* __restrict__ Wp,
    const float* __restrict__ Wg)
{
    __shared__ __align__(16) float wsm[64 * 48];  // [c][j], j: 0-7 Wt, 8-15 Wp, 16-47 Wg
    int tid = threadIdx.x;
    for (int i = tid; i < 64 * 48; i += 256) {
        int c = i / 48, j = i % 48;
        float v;
        if (j < 8)       v = Wt[j * 64 + c];
        else if (j < 16) v = Wp[(j - 8) * 64 + c];
        else             v = Wg[(j - 16) * 64 + c];
        wsm[i] = v;
    }
    __syncthreads();

    int b = blockIdx.y;
    int p = blockIdx.x * 256 + tid;
    const float* xp = x + (size_t)b * 64 * HW_ + p;

    float acc[48];
#pragma unroll
    for (int j = 0; j < 48; j++) acc[j] = 0.f;

#pragma unroll
    for (int c = 0; c < 64; c++) {
        float xv = xp[(size_t)c * HW_];
        const float4* w4 = reinterpret_cast<const float4*>(&wsm[c * 48]);
#pragma unroll
        for (int jj = 0; jj < 12; jj++) {
            float4 w = w4[jj];
            acc[jj * 4 + 0] = fmaf(xv, w.x, acc[jj * 4 + 0]);
            acc[jj * 4 + 1] = fmaf(xv, w.y, acc[jj * 4 + 1]);
            acc[jj * 4 + 2] = fmaf(xv, w.z, acc[jj * 4 + 2]);
            acc[jj * 4 + 3] = fmaf(xv, w.w, acc[jj * 4 + 3]);
        }
    }

    size_t pp = (size_t)b * HW_ + p;
    reinterpret_cast<uint4*>(d_theta)[pp]   = pack8(&acc[0]);
    reinterpret_cast<uint4*>(d_phi_pre)[pp] = pack8(&acc[8]);
    uint4* gdst = reinterpret_cast<uint4*>(d_g_pre) + pp * 4;
    gdst[0] = pack8(&acc[16]);
    gdst[1] = pack8(&acc[24]);
    gdst[2] = pack8(&acc[32]);
    gdst[3] = pack8(&acc[40]);
}

// ---------------- kernel 2: 2x2 max pool + transpose g ----------------
// grid (4, 16) x 256; thread = one pooled cell s.
__global__ void __launch_bounds__(256) pool_kernel()
{
    int b = blockIdx.y;
    int s = blockIdx.x * 256 + threadIdx.x;       // 0..1023
    int i = s >> 5, j = s & 31;
    int p00 = i * 128 + j * 2;                     // (2i)*64 + 2j

    // phi: pool 8 channels
    {
        const uint4* pp = reinterpret_cast<const uint4*>(d_phi_pre) + (size_t)b * HW_;
        uint4 m = max4u(pp[p00], pp[p00 + 1], pp[p00 + 64], pp[p00 + 65]);
        reinterpret_cast<uint4*>(d_phi_t)[(size_t)b * SP_ + s] = m;
    }
    // g: pool 32 channels + transpose to [v][s]
    {
        const uint4* gp = reinterpret_cast<const uint4*>(d_g_pre) + (size_t)b * HW_ * 4;
        __nv_bfloat16* gt = d_g_t + ((size_t)b * 32 << 10) + s;
#pragma unroll
        for (int q = 0; q < 4; q++) {
            uint4 m = max4u(gp[(size_t)p00 * 4 + q],       gp[(size_t)(p00 + 1) * 4 + q],
                            gp[(size_t)(p00 + 64) * 4 + q], gp[(size_t)(p00 + 65) * 4 + q]);
            const __nv_bfloat162* h = reinterpret_cast<const __nv_bfloat162*>(&m);
#pragma unroll
            for (int e = 0; e < 4; e++) {
                int v = q * 8 + 2 * e;
                gt[(size_t)v << 10]       = h[e].x;
                gt[(size_t)(v + 1) << 10] = h[e].y;
            }
        }
    }
}

// ---------------- kernel 3: fused attention (QK^T -> exp -> PV), no max-sub ----------------
// grid (32, 16) x 256 threads (8 warps, 16 queries each => 128 q per CTA).
static constexpr int G_STRIDE = 1032;                       // padded key stride (bf16)
static constexpr int ATTN_SMEM = SP_ * 8 * 2 + 32 * G_STRIDE * 2;  // 16384 + 66048 = 82432

__global__ void __launch_bounds__(256) attn_kernel()
{
    extern __shared__ __align__(16) char smem[];
    __nv_bfloat16* phi_s = reinterpret_cast<__nv_bfloat16*>(smem);          // [key][8]
    __nv_bfloat16* g_s   = reinterpret_cast<__nv_bfloat16*>(smem + SP_ * 8 * 2); // [v][1032]

    int b   = blockIdx.y;
    int tid = threadIdx.x;

    // load phi tile: 1024 * 16B
    {
        const uint4* src = reinterpret_cast<const uint4*>(d_phi_t) + (size_t)b * SP_;
        uint4* dst = reinterpret_cast<uint4*>(phi_s);
        for (int i = tid; i < SP_; i += 256) dst[i] = src[i];
    }
    // load g tile: 32 rows of 128 uint4 -> padded rows of 129 uint4
    {
        const uint4* src = reinterpret_cast<const uint4*>(d_g_t) + (size_t)b * 32 * 128;
        uint4* dst = reinterpret_cast<uint4*>(g_s);
        for (int i = tid; i < 32 * 128; i += 256) {
            int v = i >> 7, col = i & 127;
            dst[v * 129 + col] = src[i];
        }
    }
    __syncthreads();

    int w    = tid >> 5;
    int lane = tid & 31;
    int g4   = lane >> 2;   // groupID (row within fragment)
    int tg   = lane & 3;    // thread-in-group
    int qb   = blockIdx.x * 128 + w * 16;
    int q0   = qb + g4;

    // A fragment: theta rows q0, q0+8, dims [2tg, 2tg+1]
    u32 a0 = *reinterpret_cast<const u32*>(d_theta + ((size_t)(b * HW_ + q0)) * 8 + 2 * tg);
    u32 a1 = *reinterpret_cast<const u32*>(d_theta + ((size_t)(b * HW_ + q0 + 8)) * 8 + 2 * tg);

    float o[16];
#pragma unroll
    for (int i = 0; i < 16; i++) o[i] = 0.f;
    float sum0 = 0.f, sum1 = 0.f;

#pragma unroll 2
    for (int kb = 0; kb < SP_; kb += 16) {
        // QK^T: two m16n8k8 over 16 keys
        u32 pb0 = *reinterpret_cast<const u32*>(phi_s + (kb + g4) * 8 + 2 * tg);
        u32 pb1 = *reinterpret_cast<const u32*>(phi_s + (kb + 8 + g4) * 8 + 2 * tg);
        float s1[4], s2[4];
        mma_k8(s1, a0, a1, pb0);
        mma_k8(s2, a0, a1, pb1);

        // exp (no max-subtraction: scores bounded ~|4|)
#pragma unroll
        for (int i = 0; i < 4; i++) { s1[i] = __expf(s1[i]); s2[i] = __expf(s2[i]); }
        sum0 += s1[0] + s1[1] + s2[0] + s2[1];   // row q0
        sum1 += s1[2] + s1[3] + s2[2] + s2[3];   // row q0+8

        // repack C-fragments as A-fragment of PV mma
        u32 pa0 = packbf(s1[0], s1[1]);
        u32 pa1 = packbf(s1[2], s1[3]);
        u32 pa2 = packbf(s2[0], s2[1]);
        u32 pa3 = packbf(s2[2], s2[3]);

        // PV: 4x m16n8k16 across v=32
        const __nv_bfloat16* grow = g_s + g4 * G_STRIDE + kb + 2 * tg;
#pragma unroll
        for (int j = 0; j < 4; j++) {
            u32 gb0 = *reinterpret_cast<const u32*>(grow + j * 8 * G_STRIDE);
            u32 gb1 = *reinterpret_cast<const u32*>(grow + j * 8 * G_STRIDE + 8);
            mma_k16(&o[4 * j], pa0, pa1, pa2, pa3, gb0, gb1);
        }
    }

    // reduce row sums across the quad
    sum0 += __shfl_xor_sync(0xffffffffu, sum0, 1);
    sum0 += __shfl_xor_sync(0xffffffffu, sum0, 2);
    sum1 += __shfl_xor_sync(0xffffffffu, sum1, 1);
    sum1 += __shfl_xor_sync(0xffffffffu, sum1, 2);
    float inv0 = __frcp_rn(sum0);
    float inv1 = __frcp_rn(sum1);

    float* ob = d_o + (size_t)b * HW_ * 32;
#pragma unroll
    for (int j = 0; j < 4; j++) {
        int v = 8 * j + 2 * tg;
        float2 r0 = make_float2(o[4 * j + 0] * inv0, o[4 * j + 1] * inv0);
        float2 r1 = make_float2(o[4 * j + 2] * inv1, o[4 * j + 3] * inv1);
        *reinterpret_cast<float2*>(ob + (size_t)q0 * 32 + v)       = r0;
        *reinterpret_cast<float2*>(ob + (size_t)(q0 + 8) * 32 + v) = r1;
    }
}

// ---------------- kernel 4: out = gamma * (Wo @ o) + x ----------------
// grid (16, 16) x 256; thread = one pixel, 64 output channels.
__global__ void __launch_bounds__(256) out_kernel(
    const float* __restrict__ x, const float* __restrict__ Wo,
    const float* __restrict__ gamma_p, float* __restrict__ out)
{
    __shared__ __align__(16) float wsm[32 * 64];  // [v][c]
    int tid = threadIdx.x;
    for (int i = tid; i < 32 * 64; i += 256) {
        int v = i >> 6, c = i & 63;
        wsm[i] = Wo[c * 32 + v];
    }
    __syncthreads();

    int b = blockIdx.y;
    int p = blockIdx.x * 256 + tid;

    const float4* op = reinterpret_cast<const float4*>(d_o + ((size_t)(b * HW_ + p)) * 32);
    float ov[32];
#pragma unroll
    for (int q = 0; q < 8; q++) {
        float4 t = op[q];
        ov[q * 4 + 0] = t.x; ov[q * 4 + 1] = t.y;
        ov[q * 4 + 2] = t.z; ov[q * 4 + 3] = t.w;
    }

    float acc[64];
#pragma unroll
    for (int c = 0; c < 64; c++) acc[c] = 0.f;
#pragma unroll
    for (int v = 0; v < 32; v++) {
        float s = ov[v];
        const float4* w4 = reinterpret_cast<const float4*>(&wsm[v * 64]);
#pragma unroll
        for (int cc = 0; cc < 16; cc++) {
            float4 w = w4[cc];
            acc[cc * 4 + 0] = fmaf(s, w.x, acc[cc * 4 + 0]);
            acc[cc * 4 + 1] = fmaf(s, w.y, acc[cc * 4 + 1]);
            acc[cc * 4 + 2] = fmaf(s, w.z, acc[cc * 4 + 2]);
            acc[cc * 4 + 3] = fmaf(s, w.w, acc[cc * 4 + 3]);
        }
    }

    float gm = *gamma_p;
    const float* xb = x + (size_t)b * 64 * HW_ + p;
    float* ob = out + (size_t)b * 64 * HW_ + p;
#pragma unroll
    for (int c = 0; c < 64; c++) {
        ob[(size_t)c * HW_] = fmaf(gm, acc[c], xb[(size_t)c * HW_]);
    }
}

// ---------------- launch ----------------
extern "C" void kernel_launch(void* const* d_in, const int* in_sizes, int n_in,
                              void* d_out, int out_size)
{
    const float* x     = (const float*)d_in[0];
    const float* Wt    = (const float*)d_in[1];
    const float* Wp    = (const float*)d_in[2];
    const float* Wg    = (const float*)d_in[3];
    const float* Wo    = (const float*)d_in[4];
    const float* gamma = (const float*)d_in[5];
    float* out = (float*)d_out;

    proj_kernel<<<dim3(16, 16), 256>>>(x, Wt, Wp, Wg);
    pool_kernel<<<dim3(4, 16), 256>>>();

    cudaFuncSetAttribute(attn_kernel, cudaFuncAttributeMaxDynamicSharedMemorySize, ATTN_SMEM);
    attn_kernel<<<dim3(32, 16), 256, ATTN_SMEM>>>();

    out_kernel<<<dim3(16, 16), 256>>>(x, Wo, gamma, out);
}